// round 8
// baseline (speedup 1.0000x reference)
#include <cuda_runtime.h>
#include <cstdint>

// Problem constants
#define BB 32
#define II 2048
#define OO 32
#define CC 16
#define UU 32
#define KTOT (II*CC)        // 32768

// D[1024(m=o*32+u), 32(n=b)] = W^T * X^T
#define MT  8               // m-tiles of 128 rows (4 o x 32 u)
#define KS  64              // k-splits
#define KC  32              // k per chunk (2 i's)
#define NCH (KTOT/(KS*KC))  // 16 chunks per block
#define NSEG 16             // reduce stage-1 segments

#define ISTRIDE (OO*CC*UU)  // floats between consecutive i in w

// Scratch: partials [mt][ks][m_local(128)][b(32)] = 8MB, stage1 = 2MB
__device__ float g_spart[(size_t)MT * KS * 128 * BB];
__device__ float g_s1[(size_t)OO * NSEG * UU * BB];

// ---------------------------------------------------------------------------
__device__ __forceinline__ uint32_t smem_u32(const void* p) {
    uint32_t a;
    asm("{ .reg .u64 t; cvta.to.shared.u64 t, %1; cvt.u32.u64 %0, t; }"
        : "=r"(a) : "l"(p));
    return a;
}
// pack two f32 -> bf16x2, lo in bits[15:0]
__device__ __forceinline__ uint32_t pack_bf16(float lo, float hi) {
    uint32_t r;
    asm("cvt.rn.bf16x2.f32 %0, %1, %2;" : "=r"(r) : "f"(hi), "f"(lo));
    return r;
}
__device__ __forceinline__ void ldsm_x4(uint32_t* r, uint32_t addr) {
    asm volatile("ldmatrix.sync.aligned.m8n8.x4.shared.b16 {%0,%1,%2,%3}, [%4];"
                 : "=r"(r[0]), "=r"(r[1]), "=r"(r[2]), "=r"(r[3]) : "r"(addr));
}
__device__ __forceinline__ void ldsm_x4_t(uint32_t* r, uint32_t addr) {
    asm volatile("ldmatrix.sync.aligned.m8n8.x4.trans.shared.b16 {%0,%1,%2,%3}, [%4];"
                 : "=r"(r[0]), "=r"(r[1]), "=r"(r[2]), "=r"(r[3]) : "r"(addr));
}
__device__ __forceinline__ void mma_bf16(float* d, const uint32_t* a,
                                         uint32_t b0, uint32_t b1) {
    asm volatile(
        "mma.sync.aligned.m16n8k16.row.col.f32.bf16.bf16.f32 "
        "{%0,%1,%2,%3}, {%4,%5,%6,%7}, {%8,%9}, {%0,%1,%2,%3};"
        : "+f"(d[0]), "+f"(d[1]), "+f"(d[2]), "+f"(d[3])
        : "r"(a[0]), "r"(a[1]), "r"(a[2]), "r"(a[3]), "r"(b0), "r"(b1));
}

// B (64B rows): 16B group j of row r -> r*64 + (j ^ ((r>>1)&3))*16
__device__ __forceinline__ uint32_t sw64(int row, int grp) {
    return (uint32_t)(row * 64 + ((grp ^ ((row >> 1) & 3)) << 4));
}
// A ([k][m], 256B rows): 16B m-group g of k-row r -> r*256 + (g ^ (r&7))*16
__device__ __forceinline__ uint32_t swA(int krow, int mgrp) {
    return (uint32_t)(krow * 256 + ((mgrp ^ (krow & 7)) << 4));
}

// ---------------------------------------------------------------------------
// GEMM: grid (MT, KS), 128 threads, 4 CTAs/SM.
// A smem stored [k(32)][m(128)] bf16 (hi/lo), filled from float4 loads along u
// (u == m direction), consumed via ldmatrix.x4.trans. B as before ([b][k]).
// ---------------------------------------------------------------------------
__global__ void __launch_bounds__(128, 4) gemm_tc(const float* __restrict__ w,
                                                  const float* __restrict__ x) {
    __shared__ __align__(128) uint8_t A_HI[2][32 * 256];  // [k][m] bf16
    __shared__ __align__(128) uint8_t A_LO[2][32 * 256];
    __shared__ __align__(128) uint8_t B_HI[2][32 * 64];   // [b][k] bf16
    __shared__ __align__(128) uint8_t B_LO[2][32 * 64];

    const int mt   = blockIdx.x;
    const int ks   = blockIdx.y;
    const int tid  = threadIdx.x;
    const int wid  = tid >> 5;
    const int lane = tid & 31;

    // A-convert mapping: thread has fixed (o, u-quad), covers 8 k-rows.
    const int mq  = tid & 31;          // m-quad 0..31 (o_local = mq>>3, uq = mq&7)
    const int lk0 = tid >> 5;          // first local k row (0..3), stride 4
    const int oA  = mt * 4 + (mq >> 3);
    const int u0  = (mq & 7) * 4;
    const int m0  = mq * 4;            // m = o_local*32 + u0

    const int xb = tid >> 2, xq = tid & 3;   // B-convert mapping

    // w base: (i = ks*NCH*2, o = oA, c = lk0, u = u0); chunk t adds t*2*ISTRIDE
    const float* const wbase =
        w + (((size_t)(ks * NCH * 2) * OO + oA) * CC + lk0) * UU + u0;
    const float4* const xbase =
        (const float4*)(x + (size_t)xb * KTOT + ks * (NCH * KC)) + xq * 2;

    float4 va[8];
    float4 vb[2];

    // prefetch chunk 0: va[r] = w(i0 + r/4, c = lk0 + 4*(r%4)... see below)
#pragma unroll
    for (int r = 0; r < 4; r++) va[r]     = *(const float4*)(wbase + r * 4 * UU);
#pragma unroll
    for (int r = 0; r < 4; r++) va[4 + r] = *(const float4*)(wbase + ISTRIDE + r * 4 * UU);
    vb[0] = xbase[0];
    vb[1] = xbase[1];

    float acc[2][4][4];
#pragma unroll
    for (int a = 0; a < 2; a++)
#pragma unroll
        for (int b = 0; b < 4; b++)
#pragma unroll
            for (int c = 0; c < 4; c++) acc[a][b][c] = 0.f;

    for (int t = 0; t < NCH; t++) {
        const int p = t & 1;

        // ---- convert & store chunk t: item r -> k-row lk0 + 4r, m = m0..m0+3
#pragma unroll
        for (int r = 0; r < 8; r++) {
            const int lk = lk0 + 4 * r;   // r<4: i0 rows, r>=4: i0+1 rows (lk 16..31)
            float4 v = va[r];
            uint32_t h01 = pack_bf16(v.x, v.y);
            uint32_t h23 = pack_bf16(v.z, v.w);
            float r0 = v.x - __uint_as_float(h01 << 16);
            float r1 = v.y - __uint_as_float(h01 & 0xffff0000u);
            float r2 = v.z - __uint_as_float(h23 << 16);
            float r3 = v.w - __uint_as_float(h23 & 0xffff0000u);
            uint32_t l01 = pack_bf16(r0, r1);
            uint32_t l23 = pack_bf16(r2, r3);
            // byte addr: row lk, m-group mq>>1, half mq&1
            const uint32_t off = swA(lk, mq >> 1) + (mq & 1) * 8;
            *(uint2*)(A_HI[p] + off) = make_uint2(h01, h23);
            *(uint2*)(A_LO[p] + off) = make_uint2(l01, l23);
        }
        {   // B: thread's 8 floats = k group xq of row xb
            float v[8] = {vb[0].x, vb[0].y, vb[0].z, vb[0].w,
                          vb[1].x, vb[1].y, vb[1].z, vb[1].w};
            uint32_t h[4], l[4];
#pragma unroll
            for (int q = 0; q < 4; q++) {
                h[q] = pack_bf16(v[2 * q], v[2 * q + 1]);
                float r0 = v[2 * q]     - __uint_as_float(h[q] << 16);
                float r1 = v[2 * q + 1] - __uint_as_float(h[q] & 0xffff0000u);
                l[q] = pack_bf16(r0, r1);
            }
            const uint32_t off = sw64(xb, xq);
            *(uint4*)(B_HI[p] + off) = make_uint4(h[0], h[1], h[2], h[3]);
            *(uint4*)(B_LO[p] + off) = make_uint4(l[0], l[1], l[2], l[3]);
        }

        __syncthreads();   // buf[p] ready for all warps

        // ---- prefetch chunk t+1 (hides under MMA)
        if (t + 1 < NCH) {
            const float* wp = wbase + (size_t)((t + 1) * 2) * ISTRIDE;
#pragma unroll
            for (int r = 0; r < 4; r++) va[r]     = *(const float4*)(wp + r * 4 * UU);
#pragma unroll
            for (int r = 0; r < 4; r++) va[4 + r] = *(const float4*)(wp + ISTRIDE + r * 4 * UU);
            const float4* xp = xbase + (t + 1) * (KC / 4);
            vb[0] = xp[0];
            vb[1] = xp[1];
        }

        // ---- MMA: 2 k-tiles of 16
        const uint32_t aHi = smem_u32(A_HI[p]), aLo = smem_u32(A_LO[p]);
        const uint32_t bHi = smem_u32(B_HI[p]), bLo = smem_u32(B_LO[p]);

        // A (trans): lanes 0-7 tile(m+0,k+0), 8-15 tile(m+8,k+0),
        //            16-23 tile(m+0,k+8), 24-31 tile(m+8,k+8)
        const int a_koff = ((lane >> 4) & 1) * 8 + (lane & 7);
        const int a_moff = ((lane >> 3) & 1) * 8;
#pragma unroll
        for (int kt = 0; kt < 2; kt++) {
            uint32_t ahi[2][4], alo[2][4], bhiR[2][4], bloR[2][4];

            const int krow = kt * 16 + a_koff;
#pragma unroll
            for (int m2 = 0; m2 < 2; m2++) {
                const int mcol = wid * 32 + m2 * 16 + a_moff;
                const uint32_t off = swA(krow, mcol >> 3);
                ldsm_x4_t(ahi[m2], aHi + off);
                ldsm_x4_t(alo[m2], aLo + off);
            }
            const int bn  = (lane & 7) + ((lane >> 4) & 1) * 8;
            const int bkg = 2 * kt + ((lane >> 3) & 1);
#pragma unroll
            for (int g2 = 0; g2 < 2; g2++) {
                const int n = g2 * 16 + bn;
                const uint32_t off = sw64(n, bkg);
                ldsm_x4(bhiR[g2], bHi + off);
                ldsm_x4(bloR[g2], bLo + off);
            }
#pragma unroll
            for (int m2 = 0; m2 < 2; m2++)
#pragma unroll
                for (int nt = 0; nt < 4; nt++) {
                    const uint32_t bh0 = bhiR[nt >> 1][(nt & 1) * 2];
                    const uint32_t bh1 = bhiR[nt >> 1][(nt & 1) * 2 + 1];
                    const uint32_t bl0 = bloR[nt >> 1][(nt & 1) * 2];
                    const uint32_t bl1 = bloR[nt >> 1][(nt & 1) * 2 + 1];
                    mma_bf16(acc[m2][nt], ahi[m2], bh0, bh1);
                    mma_bf16(acc[m2][nt], alo[m2], bh0, bh1);
                    mma_bf16(acc[m2][nt], ahi[m2], bl0, bl1);
                }
        }
        // buf[p] is rewritten only at t+2, after every warp passed sync(t+1).
    }

    // ---- epilogue: D fragments -> g_spart[(mt*KS+ks)][m_local][b]
    float* outp = g_spart + ((size_t)(mt * KS + ks)) * (128 * BB);
#pragma unroll
    for (int m2 = 0; m2 < 2; m2++)
#pragma unroll
        for (int nt = 0; nt < 4; nt++) {
            const int r0 = wid * 32 + m2 * 16 + (lane >> 2);
            const int c  = nt * 8 + 2 * (lane & 3);
            *(float2*)(outp + (size_t)r0 * BB + c) =
                make_float2(acc[m2][nt][0], acc[m2][nt][1]);
            *(float2*)(outp + (size_t)(r0 + 8) * BB + c) =
                make_float2(acc[m2][nt][2], acc[m2][nt][3]);
        }
}

// ---------------------------------------------------------------------------
// Reduce stage 1: grid (OO, NSEG), 256 threads, float4. Sums KS/NSEG=4 splits.
// ---------------------------------------------------------------------------
__global__ void __launch_bounds__(256) reduce1() {
    const int o = blockIdx.x, seg = blockIdx.y;
    const int t = threadIdx.x;
    const int uu2 = t >> 3, q = t & 7;
    const int mt = o >> 2;
    const int mrow = (o & 3) * 32 + uu2;

    const float4* p = (const float4*)(g_spart +
        (((size_t)mt * KS + seg * (KS / NSEG)) * 128 + mrow) * BB) + q;
    float4 s = make_float4(0.f, 0.f, 0.f, 0.f);
#pragma unroll
    for (int k = 0; k < KS / NSEG; k++) {
        float4 v = p[(size_t)k * (128 * BB / 4)];
        s.x += v.x; s.y += v.y; s.z += v.z; s.w += v.w;
    }
    *((float4*)(g_s1 + (((size_t)o * NSEG + seg) * UU + uu2) * BB) + q) = s;
}

// ---------------------------------------------------------------------------
// Reduce stage 2 + squash: grid = OO, 256 threads.
// ---------------------------------------------------------------------------
__global__ void __launch_bounds__(256) reduce2(float* __restrict__ out) {
    const int o = blockIdx.x;
    const int t = threadIdx.x;
    const int uu2 = t >> 3, q = t & 7;

    __shared__ float sblk[UU * 36];    // [u][b], pad 36
    __shared__ float scale_s[BB];

    float4 s = make_float4(0.f, 0.f, 0.f, 0.f);
#pragma unroll
    for (int seg = 0; seg < NSEG; seg++) {
        float4 v = *((const float4*)(g_s1 +
            (((size_t)o * NSEG + seg) * UU + uu2) * BB) + q);
        s.x += v.x; s.y += v.y; s.z += v.z; s.w += v.w;
    }
    sblk[uu2 * 36 + 4 * q + 0] = s.x;
    sblk[uu2 * 36 + 4 * q + 1] = s.y;
    sblk[uu2 * 36 + 4 * q + 2] = s.z;
    sblk[uu2 * 36 + 4 * q + 3] = s.w;
    __syncthreads();

    if (t < BB) {
        float nsq = 0.f;
#pragma unroll
        for (int uv = 0; uv < UU; uv++) {
            float sv = sblk[uv * 36 + t];
            nsq += sv * sv;
        }
        scale_s[t] = sqrtf(nsq) / (1.0f + nsq);
    }
    __syncthreads();

#pragma unroll
    for (int r = 0; r < 4; r++) {
        const int gid = t + 256 * r;           // b2*32 + u2
        const int b2 = gid >> 5, u2 = gid & 31;
        out[(size_t)b2 * (OO * UU) + o * UU + u2] =
            sblk[u2 * 36 + b2] * scale_s[b2];
    }
}

// ---------------------------------------------------------------------------
extern "C" void kernel_launch(void* const* d_in, const int* in_sizes, int n_in,
                              void* d_out, int out_size) {
    const float* x = (const float*)d_in[0];
    const float* w = (const float*)d_in[1];
    if (n_in >= 2 && in_sizes[0] > in_sizes[1]) {   // guard input ordering
        x = (const float*)d_in[1];
        w = (const float*)d_in[0];
    }

    gemm_tc<<<dim3(MT, KS), 128>>>(w, x);
    reduce1<<<dim3(OO, NSEG), 256>>>();
    reduce2<<<OO, 256>>>((float*)d_out);
}